// round 10
// baseline (speedup 1.0000x reference)
#include <cuda_runtime.h>

// R10: load-path experiment. Every prior kernel loaded x via const __restrict__
// -> ld.global.nc (non-coherent path). Evidence that L2 tagging of the load
// path matters across graph replays: __ldcs (evict-first) regressed warm time
// to 8.93us; evict_last (no carveout -> near no-op) ~= baseline; and warm
// replay time has ALWAYS equaled cold time +1us, i.e. x never stays L2-resident
// between replays despite 32MB << 126MB. Hypothesis: nc fills don't persist.
// This round: plain coherent ld.global / st.global, default eviction, same
// proven shape (EPT=4, 1024 blocks, MUFU cos).
//
// Math (fixed since R1): RZ phases cancel in |amp|^2 (params unused); CNOT
// chain is XOR-linear; out = [c1c2c3, c0c1, c0c1c2, c0c1c2c3], c_j=cos(x_j).

#define BLOCK 256
#define EPT   4   // float4 per thread -> 1024 blocks for 2^20 rows

__global__ void __launch_bounds__(BLOCK)
_VariationalQHead_65481071396152_kernel(float4* x, float4* out)   // no const, no restrict
{
    int base = blockIdx.x * (BLOCK * EPT) + threadIdx.x;

    float4 v[EPT];
#pragma unroll
    for (int k = 0; k < EPT; k++)
        v[k] = x[base + k * BLOCK];          // plain coherent LDG.128

#pragma unroll
    for (int k = 0; k < EPT; k++) {
        float c0 = __cosf(v[k].x);
        float c1 = __cosf(v[k].y);
        float c2 = __cosf(v[k].z);
        float c3 = __cosf(v[k].w);
        float c01  = c0 * c1;
        float c012 = c01 * c2;
        float4 o;
        o.x = c1 * c2 * c3;
        o.y = c01;
        o.z = c012;
        o.w = c012 * c3;
        out[base + k * BLOCK] = o;           // plain STG.128
    }
}

// Generic fallback for any residue (dataset is 2^20 rows -> unused there).
__global__ void _VQH_tail_kernel(float4* x, float4* out, int start, int n)
{
    int i = start + blockIdx.x * blockDim.x + threadIdx.x;
    if (i < n) {
        float4 v = x[i];
        float c0 = __cosf(v.x), c1 = __cosf(v.y), c2 = __cosf(v.z), c3 = __cosf(v.w);
        float c01 = c0 * c1, c012 = c01 * c2;
        out[i] = make_float4(c1 * c2 * c3, c01, c012, c012 * c3);
    }
}

extern "C" void kernel_launch(void* const* d_in, const int* in_sizes, int n_in,
                              void* d_out, int out_size)
{
    float4* x = (float4*)d_in[0];               // x: [B,4] float32
    float4* out = (float4*)d_out;               // out: [B,4] float32
    int n4 = in_sizes[0] / 4;                   // batch rows (float4 count)

    int per_block = BLOCK * EPT;
    int grid = n4 / per_block;                  // full tiles, no predicates
    if (grid > 0)
        _VariationalQHead_65481071396152_kernel<<<grid, BLOCK>>>(x, out);

    int rem_start = grid * per_block;
    int rem = n4 - rem_start;
    if (rem > 0)
        _VQH_tail_kernel<<<(rem + 255) / 256, 256>>>(x, out, rem_start, n4);
}